// round 2
// baseline (speedup 1.0000x reference)
#include <cuda_runtime.h>
#include <math.h>

// Problem constants (shapes from reference setup_inputs)
#define D        256
#define NSPLIT   16
#define BM       128
#define BN       128
#define BK       16
#define BM2      32
#define BN2      64

// Static device scratch (no allocation allowed)
__device__ float g_pmax[4096 * NSPLIT];
__device__ int   g_pidx[4096 * NSPLIT];
__device__ int   g_nn[4096];
__device__ float g_logits[2u * 2048u * 2048u];   // 32 MB: rows 0..2047 = ab, 2048..4095 = ba
__device__ float g_rowterm[4096];

// ---- packed fp32x2 helpers (FFMA2: ptxas won't emit from C++, PTX-only) ----
static __device__ __forceinline__ unsigned long long pack2(float x) {
    unsigned long long r;
    asm("mov.b64 %0, {%1, %1};" : "=l"(r) : "f"(x));
    return r;
}
static __device__ __forceinline__ void fma2(unsigned long long& d,
                                            unsigned long long a,
                                            unsigned long long b) {
    asm("fma.rn.f32x2 %0, %1, %2, %0;" : "+l"(d) : "l"(a), "l"(b));
}
static __device__ __forceinline__ float lo32(unsigned long long v) {
    return __int_as_float((int)(unsigned)(v & 0xffffffffull));
}
static __device__ __forceinline__ float hi32(unsigned long long v) {
    return __int_as_float((int)(unsigned)(v >> 32));
}

// ============================================================================
// Stage 1: sim = emb @ queue^T, fused running argmax per row.
// Grid (B/BM, NSPLIT). Each block: BM emb rows vs one Q/NSPLIT slice of queue,
// BN=128 queue rows per chunk, 8x8 per-thread tile, fp32x2 packed FMA.
// ============================================================================
__global__ __launch_bounds__(256, 2)
void argmax_kernel(const float* __restrict__ emb, const float* __restrict__ queue,
                   int B, int Q)
{
    __shared__ float As[BK][BM + 4];   // k-major, padded
    __shared__ float Bs[BK][BN + 4];
    __shared__ float cval[BM][16];
    __shared__ int   cidx[BM][16];
    __shared__ float rbv[BM];
    __shared__ int   rbi[BM];

    const int tid = threadIdx.x;
    const int tx  = tid & 15;   // 0..15 -> cols tx*8..tx*8+7
    const int ty  = tid >> 4;   // 0..15 -> rows ty*8..ty*8+7
    const int m0  = blockIdx.x * BM;
    const int nchunk = Q / NSPLIT;
    const int nstart = blockIdx.y * nchunk;
    const int nend   = nstart + nchunk;

    if (tid < BM) { rbv[tid] = -INFINITY; rbi[tid] = 0x7fffffff; }

    const int lrow = tid >> 1;        // 0..127
    const int lk   = (tid & 1) * 8;   // 0 or 8

    for (int n0 = nstart; n0 < nend; n0 += BN) {
        unsigned long long acc[8][4];
        #pragma unroll
        for (int i = 0; i < 8; i++)
            #pragma unroll
            for (int j = 0; j < 4; j++) acc[i][j] = 0ull;

        for (int k0 = 0; k0 < D; k0 += BK) {
            float4 a0 = *(const float4*)&emb[(size_t)(m0 + lrow) * D + k0 + lk];
            float4 a1 = *(const float4*)&emb[(size_t)(m0 + lrow) * D + k0 + lk + 4];
            float4 b0 = *(const float4*)&queue[(size_t)(n0 + lrow) * D + k0 + lk];
            float4 b1 = *(const float4*)&queue[(size_t)(n0 + lrow) * D + k0 + lk + 4];
            __syncthreads();
            As[lk + 0][lrow] = a0.x; As[lk + 1][lrow] = a0.y;
            As[lk + 2][lrow] = a0.z; As[lk + 3][lrow] = a0.w;
            As[lk + 4][lrow] = a1.x; As[lk + 5][lrow] = a1.y;
            As[lk + 6][lrow] = a1.z; As[lk + 7][lrow] = a1.w;
            Bs[lk + 0][lrow] = b0.x; Bs[lk + 1][lrow] = b0.y;
            Bs[lk + 2][lrow] = b0.z; Bs[lk + 3][lrow] = b0.w;
            Bs[lk + 4][lrow] = b1.x; Bs[lk + 5][lrow] = b1.y;
            Bs[lk + 6][lrow] = b1.z; Bs[lk + 7][lrow] = b1.w;
            __syncthreads();
            #pragma unroll
            for (int k = 0; k < BK; k++) {
                float4 av0 = *(const float4*)&As[k][ty * 8];
                float4 av1 = *(const float4*)&As[k][ty * 8 + 4];
                ulonglong2 bv0 = *(const ulonglong2*)&Bs[k][tx * 8];
                ulonglong2 bv1 = *(const ulonglong2*)&Bs[k][tx * 8 + 4];
                unsigned long long ap[8];
                ap[0] = pack2(av0.x); ap[1] = pack2(av0.y);
                ap[2] = pack2(av0.z); ap[3] = pack2(av0.w);
                ap[4] = pack2(av1.x); ap[5] = pack2(av1.y);
                ap[6] = pack2(av1.z); ap[7] = pack2(av1.w);
                #pragma unroll
                for (int i = 0; i < 8; i++) {
                    fma2(acc[i][0], ap[i], bv0.x);
                    fma2(acc[i][1], ap[i], bv0.y);
                    fma2(acc[i][2], ap[i], bv1.x);
                    fma2(acc[i][3], ap[i], bv1.y);
                }
            }
        }

        // per-thread: best over its 8 cols for each of its 8 rows
        #pragma unroll
        for (int i = 0; i < 8; i++) {
            float bv = -INFINITY; int bi = 0;
            #pragma unroll
            for (int j = 0; j < 4; j++) {
                int c0 = n0 + tx * 8 + j * 2;
                float v0 = lo32(acc[i][j]);
                float v1 = hi32(acc[i][j]);
                if (v0 > bv) { bv = v0; bi = c0; }       // ascending cols + strict >
                if (v1 > bv) { bv = v1; bi = c0 + 1; }   //  => first occurrence kept
            }
            cval[ty * 8 + i][tx] = bv;
            cidx[ty * 8 + i][tx] = bi;
        }
        __syncthreads();
        if (tid < BM) {
            float bv = rbv[tid]; int bi = rbi[tid];
            #pragma unroll
            for (int t = 0; t < 16; t++) {
                float v = cval[tid][t]; int id = cidx[tid][t];
                if (v > bv || (v == bv && id < bi)) { bv = v; bi = id; }
            }
            rbv[tid] = bv; rbi[tid] = bi;
        }
        __syncthreads();
    }

    if (tid < BM) {
        g_pmax[(size_t)(m0 + tid) * NSPLIT + blockIdx.y] = rbv[tid];
        g_pidx[(size_t)(m0 + tid) * NSPLIT + blockIdx.y] = rbi[tid];
    }
}

// Merge the NSPLIT partial argmaxes per row (ascending split = ascending index
// range, strict > keeps the first occurrence, matching jnp.argmax).
__global__ void merge_argmax_kernel(int B)
{
    int i = blockIdx.x * blockDim.x + threadIdx.x;
    if (i >= B) return;
    float bv = -INFINITY; int bi = 0x7fffffff;
    #pragma unroll
    for (int s = 0; s < NSPLIT; s++) {
        float v = g_pmax[(size_t)i * NSPLIT + s];
        int  id = g_pidx[(size_t)i * NSPLIT + s];
        if (v > bv || (v == bv && id < bi)) { bv = v; bi = id; }
    }
    g_nn[i] = bi;
}

// ============================================================================
// Stage 2a: logits[s][i][j] = 10 * dot(queue[nn[s*half+i]], preds[(1-s)*half+j])
// Grid (half/BM2, half/BN2, 2). A rows gathered through nn indices.
// ============================================================================
__global__ __launch_bounds__(256)
void logits_kernel(const float* __restrict__ queue, const float* __restrict__ preds,
                   int half)
{
    __shared__ int   idx_s[BM2];
    __shared__ float As[BK][BM2 + 2];
    __shared__ float Bs[BK][BN2 + 4];

    const int tid = threadIdx.x;
    const int tx = tid & 15;   // cols tx*4..+3
    const int ty = tid >> 4;   // rows ty*2..+1
    const int s  = blockIdx.z;
    const int m0 = blockIdx.x * BM2;
    const int n0 = blockIdx.y * BN2;

    if (tid < BM2) idx_s[tid] = g_nn[s * half + m0 + tid];
    __syncthreads();

    const float* pb = preds + (size_t)(1 - s) * half * D;

    const int am = tid >> 3;         // 0..31
    const int ak = (tid & 7) * 2;    // 0..14
    const int bm = tid >> 2;         // 0..63
    const int bk = (tid & 3) * 4;    // 0..12

    float acc[2][4] = {};

    for (int k0 = 0; k0 < D; k0 += BK) {
        float2 av = *(const float2*)&queue[(size_t)idx_s[am] * D + k0 + ak];
        float4 bv = *(const float4*)&pb[(size_t)(n0 + bm) * D + k0 + bk];
        __syncthreads();
        As[ak + 0][am] = av.x; As[ak + 1][am] = av.y;
        Bs[bk + 0][bm] = bv.x; Bs[bk + 1][bm] = bv.y;
        Bs[bk + 2][bm] = bv.z; Bs[bk + 3][bm] = bv.w;
        __syncthreads();
        #pragma unroll
        for (int k = 0; k < BK; k++) {
            float2 a = *(const float2*)&As[k][ty * 2];
            float4 b = *(const float4*)&Bs[k][tx * 4];
            acc[0][0] += a.x * b.x; acc[0][1] += a.x * b.y;
            acc[0][2] += a.x * b.z; acc[0][3] += a.x * b.w;
            acc[1][0] += a.y * b.x; acc[1][1] += a.y * b.y;
            acc[1][2] += a.y * b.z; acc[1][3] += a.y * b.w;
        }
    }

    #pragma unroll
    for (int i = 0; i < 2; i++) {
        int row = s * half + m0 + ty * 2 + i;
        float4 o = make_float4(acc[i][0] * 10.f, acc[i][1] * 10.f,
                               acc[i][2] * 10.f, acc[i][3] * 10.f);
        *(float4*)&g_logits[(size_t)row * half + n0 + tx * 4] = o;
    }
}

// ============================================================================
// Stage 2b: per-row  logsumexp(row) - row[diag]   (deterministic reductions)
// ============================================================================
__global__ __launch_bounds__(256)
void ce_row_kernel(int half)
{
    __shared__ float red[8];
    const int row = blockIdx.x;
    const int tid = threadIdx.x;
    const float* L = g_logits + (size_t)row * half;

    float m = -INFINITY;
    for (int j = tid; j < half; j += 256) m = fmaxf(m, L[j]);
    #pragma unroll
    for (int o = 16; o; o >>= 1) m = fmaxf(m, __shfl_xor_sync(0xffffffffu, m, o));
    if ((tid & 31) == 0) red[tid >> 5] = m;
    __syncthreads();
    if (tid == 0) {
        float t = red[0];
        #pragma unroll
        for (int w = 1; w < 8; w++) t = fmaxf(t, red[w]);
        red[0] = t;
    }
    __syncthreads();
    const float bm = red[0];
    __syncthreads();

    float sum = 0.f;
    for (int j = tid; j < half; j += 256) sum += expf(L[j] - bm);
    #pragma unroll
    for (int o = 16; o; o >>= 1) sum += __shfl_xor_sync(0xffffffffu, sum, o);
    if ((tid & 31) == 0) red[tid >> 5] = sum;
    __syncthreads();
    if (tid == 0) {
        float t = 0.f;
        #pragma unroll
        for (int w = 0; w < 8; w++) t += red[w];
        int diag = row % half;     // labels = arange(half), same for ab and ba
        g_rowterm[row] = logf(t) + bm - L[diag];
    }
}

// loss = (mean_ab + mean_ba)/2 = sum(rowterm)/ (2*half*2)
__global__ __launch_bounds__(256)
void final_kernel(float* __restrict__ out, int total)
{
    __shared__ float red[8];
    const int tid = threadIdx.x;
    float s = 0.f;
    for (int i = tid; i < total; i += 256) s += g_rowterm[i];
    #pragma unroll
    for (int o = 16; o; o >>= 1) s += __shfl_xor_sync(0xffffffffu, s, o);
    if ((tid & 31) == 0) red[tid >> 5] = s;
    __syncthreads();
    if (tid == 0) {
        float t = 0.f;
        #pragma unroll
        for (int w = 0; w < 8; w++) t += red[w];
        out[0] = t / (float)total;
    }
}

// ============================================================================
extern "C" void kernel_launch(void* const* d_in, const int* in_sizes, int n_in,
                              void* d_out, int out_size)
{
    const float* emb   = (const float*)d_in[0];   // [B, D]
    const float* preds = (const float*)d_in[1];   // [B, D]
    const float* queue = (const float*)d_in[2];   // [Q, D], rows unit-norm

    const int B = in_sizes[0] / D;     // 4096
    const int Q = in_sizes[2] / D;     // 65536
    const int half = B / 2;            // 2048

    argmax_kernel<<<dim3(B / BM, NSPLIT), 256>>>(emb, queue, B, Q);
    merge_argmax_kernel<<<(B + 255) / 256, 256>>>(B);
    logits_kernel<<<dim3(half / BM2, half / BN2, 2), 256>>>(queue, preds, half);
    ce_row_kernel<<<2 * half, 256>>>(half);
    final_kernel<<<1, 256>>>((float*)d_out, 2 * half);
}